// round 2
// baseline (speedup 1.0000x reference)
#include <cuda_runtime.h>
#include <math.h>

// Problem constants
#define BB 4
#define TT 2048
#define CC 1024
#define HH 16
#define DD 64
#define MM (BB*TT)   // 8192 rows

// Scratch (allocation-free requirement -> __device__ globals)
__device__ float g_q[(size_t)MM * CC];   // (b,h,t,d)
__device__ float g_k[(size_t)MM * CC];   // (b,h,t,d)
__device__ float g_v[(size_t)MM * CC];   // (b,h,t,d)
__device__ float g_y[(size_t)MM * CC];   // (b,t,c)

// ---------------------------------------------------------------------------
// SGEMM: out = A(MxK) @ W(NxK)^T + bias, K=C=1024, N=C=1024
// Tile 64x64, BK=16, 256 threads (16x16), 4x4 accumulators per thread.
// SPLIT=true writes head-split layout q[(b*H+h)*T + t][d]; else row-major.
// ---------------------------------------------------------------------------
template<bool SPLIT>
__global__ void __launch_bounds__(256) sgemm_bias(const float* __restrict__ A,
                                                  const float* __restrict__ W,
                                                  const float* __restrict__ bias,
                                                  float* __restrict__ out)
{
    __shared__ float As[16 * 65];   // [k][m], padded
    __shared__ float Ws[16 * 65];   // [k][n], padded

    const int tid = threadIdx.x;
    const int tx  = tid & 15;       // n direction
    const int ty  = tid >> 4;       // m direction
    const int m0  = blockIdx.y * 64;
    const int n0  = blockIdx.x * 64;

    const int lr = tid >> 2;         // 0..63 row within tile
    const int lk = (tid & 3) * 4;    // k offset 0,4,8,12

    float acc[4][4] = {};

    const float* Arow = A + (size_t)(m0 + lr) * CC + lk;
    const float* Wrow = W + (size_t)(n0 + lr) * CC + lk;

    for (int k0 = 0; k0 < CC; k0 += 16) {
        float4 a = *(const float4*)(Arow + k0);
        float4 w = *(const float4*)(Wrow + k0);
        __syncthreads();   // previous iteration's reads complete
        As[(lk + 0) * 65 + lr] = a.x;
        As[(lk + 1) * 65 + lr] = a.y;
        As[(lk + 2) * 65 + lr] = a.z;
        As[(lk + 3) * 65 + lr] = a.w;
        Ws[(lk + 0) * 65 + lr] = w.x;
        Ws[(lk + 1) * 65 + lr] = w.y;
        Ws[(lk + 2) * 65 + lr] = w.z;
        Ws[(lk + 3) * 65 + lr] = w.w;
        __syncthreads();

        #pragma unroll
        for (int kk = 0; kk < 16; ++kk) {
            float av[4], wv[4];
            #pragma unroll
            for (int i = 0; i < 4; ++i) av[i] = As[kk * 65 + ty * 4 + i];
            #pragma unroll
            for (int j = 0; j < 4; ++j) wv[j] = Ws[kk * 65 + tx * 4 + j];
            #pragma unroll
            for (int i = 0; i < 4; ++i)
                #pragma unroll
                for (int j = 0; j < 4; ++j)
                    acc[i][j] += av[i] * wv[j];
        }
    }

    const int ncol = n0 + tx * 4;
    float4 bv4;
    bv4.x = bias[ncol + 0];
    bv4.y = bias[ncol + 1];
    bv4.z = bias[ncol + 2];
    bv4.w = bias[ncol + 3];

    #pragma unroll
    for (int i = 0; i < 4; ++i) {
        const int m = m0 + ty * 4 + i;
        float4 r;
        r.x = acc[i][0] + bv4.x;
        r.y = acc[i][1] + bv4.y;
        r.z = acc[i][2] + bv4.z;
        r.w = acc[i][3] + bv4.w;
        size_t idx;
        if (SPLIT) {
            const int b = m / TT, t = m % TT;
            const int h = ncol / DD, d = ncol % DD;
            idx = (((size_t)b * HH + h) * TT + t) * DD + d;
        } else {
            idx = (size_t)m * CC + ncol;
        }
        *(float4*)(out + idx) = r;
    }
}

// ---------------------------------------------------------------------------
// Flash attention, fp32. One CTA = one (b,h) x 64-row query tile.
// KV tiles of 64 keys; causal: only kv tiles <= q tile, mask on diagonal.
// 256 threads (16x16), thread owns 4x4 of S/P and 4x4 of O.
// ---------------------------------------------------------------------------
__global__ void __launch_bounds__(256) attn_kernel(const float* __restrict__ q,
                                                   const float* __restrict__ k,
                                                   const float* __restrict__ v,
                                                   float* __restrict__ y)
{
    extern __shared__ float smem[];
    float* Qs = smem;              // 64*64 (no pad: broadcast reads)
    float* KP = smem + 64 * 64;    // 64*65 (K tile, then reused for P)
    float* Vs = KP + 64 * 65;      // 64*64

    const int tid = threadIdx.x;
    const int tx  = tid & 15;      // key / head-dim direction
    const int ty  = tid >> 4;      // query-row direction
    const int bh  = blockIdx.y;
    const int qt0 = blockIdx.x * 64;

    const size_t base = (size_t)bh * TT * DD;
    const float* qb = q + base + (size_t)qt0 * DD;
    const float* kb = k + base;
    const float* vb = v + base;

    const int lr = tid >> 2;          // 0..63
    const int lc = (tid & 3) * 16;    // 0,16,32,48

    // Load Q tile, pre-scaled by 1/sqrt(D) = 0.125
    #pragma unroll
    for (int u = 0; u < 16; u += 4) {
        float4 t4 = *(const float4*)(qb + (size_t)lr * DD + lc + u);
        Qs[lr * 64 + lc + u + 0] = t4.x * 0.125f;
        Qs[lr * 64 + lc + u + 1] = t4.y * 0.125f;
        Qs[lr * 64 + lc + u + 2] = t4.z * 0.125f;
        Qs[lr * 64 + lc + u + 3] = t4.w * 0.125f;
    }

    float o[4][4] = {};
    float mrow[4], lrow[4];
    #pragma unroll
    for (int i = 0; i < 4; ++i) { mrow[i] = -1e30f; lrow[i] = 0.f; }

    for (int kt0 = 0; kt0 <= qt0; kt0 += 64) {
        __syncthreads();   // protect Vs/KP consumers of previous iteration
        #pragma unroll
        for (int u = 0; u < 16; u += 4) {
            float4 k4 = *(const float4*)(kb + (size_t)(kt0 + lr) * DD + lc + u);
            float4 v4 = *(const float4*)(vb + (size_t)(kt0 + lr) * DD + lc + u);
            KP[lr * 65 + lc + u + 0] = k4.x;
            KP[lr * 65 + lc + u + 1] = k4.y;
            KP[lr * 65 + lc + u + 2] = k4.z;
            KP[lr * 65 + lc + u + 3] = k4.w;
            Vs[lr * 64 + lc + u + 0] = v4.x;
            Vs[lr * 64 + lc + u + 1] = v4.y;
            Vs[lr * 64 + lc + u + 2] = v4.z;
            Vs[lr * 64 + lc + u + 3] = v4.w;
        }
        __syncthreads();

        // S = Q . K^T   (Q already scaled)
        float s[4][4] = {};
        #pragma unroll 16
        for (int d = 0; d < 64; ++d) {
            float qv[4], kv[4];
            #pragma unroll
            for (int i = 0; i < 4; ++i) qv[i] = Qs[(ty * 4 + i) * 64 + d];
            #pragma unroll
            for (int j = 0; j < 4; ++j) kv[j] = KP[(tx * 4 + j) * 65 + d];
            #pragma unroll
            for (int i = 0; i < 4; ++i)
                #pragma unroll
                for (int j = 0; j < 4; ++j)
                    s[i][j] += qv[i] * kv[j];
        }

        // causal mask on the diagonal tile
        if (kt0 == qt0) {
            #pragma unroll
            for (int i = 0; i < 4; ++i)
                #pragma unroll
                for (int j = 0; j < 4; ++j)
                    if (tx * 4 + j > ty * 4 + i) s[i][j] = -1e30f;
        }

        // online softmax: row stats live in the 16-lane tx-group (same ty)
        float alpha[4];
        #pragma unroll
        for (int i = 0; i < 4; ++i) {
            float mx = fmaxf(fmaxf(s[i][0], s[i][1]), fmaxf(s[i][2], s[i][3]));
            #pragma unroll
            for (int off = 8; off > 0; off >>= 1)
                mx = fmaxf(mx, __shfl_xor_sync(0xffffffffu, mx, off));
            float mnew = fmaxf(mrow[i], mx);
            alpha[i] = __expf(mrow[i] - mnew);
            mrow[i] = mnew;
        }

        float p[4][4];
        #pragma unroll
        for (int i = 0; i < 4; ++i) {
            float sum = 0.f;
            #pragma unroll
            for (int j = 0; j < 4; ++j) {
                p[i][j] = __expf(s[i][j] - mrow[i]);
                sum += p[i][j];
            }
            #pragma unroll
            for (int off = 8; off > 0; off >>= 1)
                sum += __shfl_xor_sync(0xffffffffu, sum, off);
            lrow[i] = lrow[i] * alpha[i] + sum;
            #pragma unroll
            for (int j = 0; j < 4; ++j) o[i][j] *= alpha[i];
        }

        __syncthreads();   // everyone done reading K from KP
        #pragma unroll
        for (int i = 0; i < 4; ++i)
            #pragma unroll
            for (int j = 0; j < 4; ++j)
                KP[(ty * 4 + i) * 65 + tx * 4 + j] = p[i][j];
        __syncthreads();

        // O += P . V
        #pragma unroll 16
        for (int ss = 0; ss < 64; ++ss) {
            float pv[4], vv[4];
            #pragma unroll
            for (int i = 0; i < 4; ++i) pv[i] = KP[(ty * 4 + i) * 65 + ss];
            #pragma unroll
            for (int j = 0; j < 4; ++j) vv[j] = Vs[ss * 64 + tx * 4 + j];
            #pragma unroll
            for (int i = 0; i < 4; ++i)
                #pragma unroll
                for (int j = 0; j < 4; ++j)
                    o[i][j] += pv[i] * vv[j];
        }
    }

    // write to (b,t,c) layout for final projection
    const int b = bh / HH, h = bh % HH;
    #pragma unroll
    for (int i = 0; i < 4; ++i) {
        const int t = qt0 + ty * 4 + i;
        const float inv = 1.f / lrow[i];
        float4 r;
        r.x = o[i][0] * inv;
        r.y = o[i][1] * inv;
        r.z = o[i][2] * inv;
        r.w = o[i][3] * inv;
        size_t idx = ((size_t)b * TT + t) * CC + h * DD + tx * 4;
        *(float4*)(y + idx) = r;
    }
}

// ---------------------------------------------------------------------------
// Launch
// ---------------------------------------------------------------------------
extern "C" void kernel_launch(void* const* d_in, const int* in_sizes, int n_in,
                              void* d_out, int out_size)
{
    (void)in_sizes; (void)n_in; (void)out_size;
    const float* x  = (const float*)d_in[0];
    const float* Wk = (const float*)d_in[1];
    const float* bk = (const float*)d_in[2];
    const float* Wq = (const float*)d_in[3];
    const float* bq = (const float*)d_in[4];
    const float* Wv = (const float*)d_in[5];
    const float* bv = (const float*)d_in[6];
    const float* Wp = (const float*)d_in[7];
    const float* bp = (const float*)d_in[8];
    float* out = (float*)d_out;

    float *pq, *pk, *pv, *py;
    cudaGetSymbolAddress((void**)&pq, g_q);
    cudaGetSymbolAddress((void**)&pk, g_k);
    cudaGetSymbolAddress((void**)&pv, g_v);
    cudaGetSymbolAddress((void**)&py, g_y);

    dim3 gb(CC / 64, MM / 64);   // (16, 128)
    dim3 tb(256);

    sgemm_bias<true><<<gb, tb>>>(x, Wq, bq, pq);
    sgemm_bias<true><<<gb, tb>>>(x, Wk, bk, pk);
    sgemm_bias<true><<<gb, tb>>>(x, Wv, bv, pv);

    const int smem_bytes = (64 * 64 + 64 * 65 + 64 * 64) * (int)sizeof(float);
    cudaFuncSetAttribute(attn_kernel, cudaFuncAttributeMaxDynamicSharedMemorySize,
                         smem_bytes);
    attn_kernel<<<dim3(TT / 64, BB * HH), 256, smem_bytes>>>(pq, pk, pv, py);

    sgemm_bias<false><<<gb, tb>>>(py, Wp, bp, out);
}

// round 5
// speedup vs baseline: 1.1852x; 1.1852x over previous
#include <cuda_runtime.h>
#include <cuda_bf16.h>
#include <math.h>
#include <stdint.h>

// Problem constants
#define BB 4
#define TT 2048
#define CC 1024
#define HH 16
#define DD 64
#define MM (BB*TT)   // 8192 rows

// ---------------------------------------------------------------------------
// Scratch (__device__ globals; no allocation allowed)
// ---------------------------------------------------------------------------
__device__ float g_q[(size_t)MM * CC];
__device__ float g_k[(size_t)MM * CC];
__device__ float g_v[(size_t)MM * CC];
__device__ float g_y[(size_t)MM * CC];

__device__ __nv_bfloat16 g_xhi[(size_t)MM * CC];
__device__ __nv_bfloat16 g_xlo[(size_t)MM * CC];
__device__ __nv_bfloat16 g_yhi[(size_t)MM * CC];
__device__ __nv_bfloat16 g_ylo[(size_t)MM * CC];
__device__ __nv_bfloat16 g_wq_hi[(size_t)CC * CC];
__device__ __nv_bfloat16 g_wq_lo[(size_t)CC * CC];
__device__ __nv_bfloat16 g_wk_hi[(size_t)CC * CC];
__device__ __nv_bfloat16 g_wk_lo[(size_t)CC * CC];
__device__ __nv_bfloat16 g_wv_hi[(size_t)CC * CC];
__device__ __nv_bfloat16 g_wv_lo[(size_t)CC * CC];
__device__ __nv_bfloat16 g_wp_hi[(size_t)CC * CC];
__device__ __nv_bfloat16 g_wp_lo[(size_t)CC * CC];

// ---------------------------------------------------------------------------
// Helpers: cp.async, ldmatrix, mma.sync (all baseline PTX, no sm_103a feats)
// ---------------------------------------------------------------------------
__device__ __forceinline__ uint32_t smem_u32(const void* p) {
    uint32_t a;
    asm("{ .reg .u64 t; cvta.to.shared.u64 t, %1; cvt.u32.u64 %0, t; }" : "=r"(a) : "l"(p));
    return a;
}
#define CP_ASYNC16(dst, src) \
    asm volatile("cp.async.cg.shared.global [%0], [%1], 16;" :: "r"(dst), "l"(src) : "memory")
#define CP_COMMIT() asm volatile("cp.async.commit_group;" ::: "memory")
#define CP_WAIT2()  asm volatile("cp.async.wait_group 2;" ::: "memory")

#define LDM_X4(r0, r1, r2, r3, a) \
    asm volatile("ldmatrix.sync.aligned.m8n8.x4.shared.b16 {%0,%1,%2,%3}, [%4];" \
        : "=r"(r0), "=r"(r1), "=r"(r2), "=r"(r3) : "r"(a))

#define MMA_BF16(acc, a, b0, b1) \
    asm volatile("mma.sync.aligned.m16n8k16.row.col.f32.bf16.bf16.f32 " \
        "{%0,%1,%2,%3},{%4,%5,%6,%7},{%8,%9},{%0,%1,%2,%3};" \
        : "+f"((acc)[0]), "+f"((acc)[1]), "+f"((acc)[2]), "+f"((acc)[3]) \
        : "r"((a)[0]), "r"((a)[1]), "r"((a)[2]), "r"((a)[3]), "r"(b0), "r"(b1))

#define SWZ(x) ((x) ^ (((x) >> 3) & 0x70))

// ---------------------------------------------------------------------------
// fp32 -> (bf16 hi, bf16 lo) split conversion
// ---------------------------------------------------------------------------
__global__ void __launch_bounds__(256) cvt_hilo(const float* __restrict__ src,
                                                __nv_bfloat16* __restrict__ hi,
                                                __nv_bfloat16* __restrict__ lo,
                                                int n4)
{
    int i = blockIdx.x * blockDim.x + threadIdx.x;
    if (i >= n4) return;
    float4 v = ((const float4*)src)[i];
    __nv_bfloat16 h0 = __float2bfloat16(v.x);
    __nv_bfloat16 h1 = __float2bfloat16(v.y);
    __nv_bfloat16 h2 = __float2bfloat16(v.z);
    __nv_bfloat16 h3 = __float2bfloat16(v.w);
    __nv_bfloat16 l0 = __float2bfloat16(v.x - __bfloat162float(h0));
    __nv_bfloat16 l1 = __float2bfloat16(v.y - __bfloat162float(h1));
    __nv_bfloat16 l2 = __float2bfloat16(v.z - __bfloat162float(h2));
    __nv_bfloat16 l3 = __float2bfloat16(v.w - __bfloat162float(h3));
    ((__nv_bfloat162*)hi)[2 * i + 0] = __nv_bfloat162(h0, h1);
    ((__nv_bfloat162*)hi)[2 * i + 1] = __nv_bfloat162(h2, h3);
    ((__nv_bfloat162*)lo)[2 * i + 0] = __nv_bfloat162(l0, l1);
    ((__nv_bfloat162*)lo)[2 * i + 1] = __nv_bfloat162(l2, l3);
}

// ---------------------------------------------------------------------------
// mma.sync GEMM: out(M,N) = A(M,K) @ B(N,K)^T + bias, hi/lo bf16 fused
//   D = Ahi*Bhi + Alo*Bhi + Ahi*Blo  accumulated in fp32 registers.
// CTA 128x128, 8 warps (2m x 4n) of 64x32, K-chunk 32, 3-stage cp.async.
// SMEM row layout (128B): [0:64) hi k0..31, [64:128) lo k0..31, SW128 swizzle.
// ---------------------------------------------------------------------------
#define KC 32
#define NCH (CC / KC)            // 32 chunks
#define STG_A 16384              // A region bytes (128 rows * 128B)
#define STG_BYTES 32768          // A + B per stage
#define GEMM_SMEM (3 * STG_BYTES)

template<bool SPLIT>
__global__ void __launch_bounds__(256) mma_gemm(
    const __nv_bfloat16* __restrict__ Ahi, const __nv_bfloat16* __restrict__ Alo,
    const __nv_bfloat16* __restrict__ Bhi, const __nv_bfloat16* __restrict__ Blo,
    const float* __restrict__ bias, float* __restrict__ out)
{
    extern __shared__ char smem[];
    const uint32_t sbase = smem_u32(smem);
    const int tid = threadIdx.x;
    const int wid = tid >> 5;
    const int lid = tid & 31;
    const int m0 = blockIdx.y * 128;
    const int n0 = blockIdx.x * 128;
    const int wm = (wid & 1) * 64;    // warp m offset
    const int wn = (wid >> 1) * 32;   // warp n offset

    // ---- loader setup: 2048 16B transfers per chunk, 8 per thread ----
    // u in [0,1024): A rows; [1024,2048): B rows. sub = u&7: 0-3 hi, 4-7 lo.
    uint32_t l_dst[8];
    const __nv_bfloat16* l_src[8];
    #pragma unroll
    for (int it = 0; it < 8; ++it) {
        const int u = it * 256 + tid;
        const bool isA = u < 1024;
        const int v = isA ? u : u - 1024;
        const int r = v >> 3, sub = v & 7;
        const int cbyte = (sub & 3) * 16 + (sub >> 2) * 64;
        l_dst[it] = sbase + (isA ? 0 : STG_A) + SWZ(r * 128 + cbyte);
        const __nv_bfloat16* basep = isA ? ((sub < 4) ? Ahi : Alo)
                                         : ((sub < 4) ? Bhi : Blo);
        const int row = isA ? (m0 + r) : (n0 + r);
        l_src[it] = basep + (size_t)row * CC + (sub & 3) * 8;
    }

    // ---- ldmatrix address setup (chunk-invariant parts) ----
    // A frag (mi, s): row = wm + mi*16 + (lid&15), cbyte = s*32 + ((lid>>4)<<4)
    // B frag (pair, s): row = wn + pair*16 + (lid&7) + ((lid>>4)<<3),
    //                   cbyte = s*32 + (((lid>>3)&1)<<4)
    uint32_t a_off[4][2], b_off[2][2];
    #pragma unroll
    for (int mi = 0; mi < 4; ++mi)
        #pragma unroll
        for (int s = 0; s < 2; ++s) {
            const int r = wm + mi * 16 + (lid & 15);
            const int cb = s * 32 + ((lid >> 4) << 4);
            a_off[mi][s] = SWZ(r * 128 + cb);
        }
    #pragma unroll
    for (int pr = 0; pr < 2; ++pr)
        #pragma unroll
        for (int s = 0; s < 2; ++s) {
            const int r = wn + pr * 16 + (lid & 7) + ((lid >> 4) << 3);
            const int cb = s * 32 + (((lid >> 3) & 1) << 4);
            b_off[pr][s] = SWZ(r * 128 + cb);
        }

    float acc[4][4][4];
    #pragma unroll
    for (int i = 0; i < 4; ++i)
        #pragma unroll
        for (int j = 0; j < 4; ++j)
            #pragma unroll
            for (int e = 0; e < 4; ++e) acc[i][j][e] = 0.f;

    // ---- prologue: issue chunks 0 and 1 ----
    #pragma unroll
    for (int c = 0; c < 2; ++c) {
        const uint32_t so = c * STG_BYTES;
        #pragma unroll
        for (int it = 0; it < 8; ++it)
            CP_ASYNC16(l_dst[it] + so, l_src[it] + c * KC);
        CP_COMMIT();
    }

    // ---- main loop ----
    for (int ch = 0; ch < NCH; ++ch) {
        const int nxt = ch + 2;
        if (nxt < NCH) {
            const uint32_t so = (nxt % 3) * STG_BYTES;
            #pragma unroll
            for (int it = 0; it < 8; ++it)
                CP_ASYNC16(l_dst[it] + so, l_src[it] + nxt * KC);
        }
        CP_COMMIT();
        CP_WAIT2();
        __syncthreads();

        const uint32_t Ab = sbase + (ch % 3) * STG_BYTES;
        const uint32_t Bb = Ab + STG_A;

        #pragma unroll
        for (int s = 0; s < 2; ++s) {
            uint32_t ah[4][4], al[4][4];
            #pragma unroll
            for (int mi = 0; mi < 4; ++mi) {
                const uint32_t ad = Ab + a_off[mi][s];
                LDM_X4(ah[mi][0], ah[mi][1], ah[mi][2], ah[mi][3], ad);
                LDM_X4(al[mi][0], al[mi][1], al[mi][2], al[mi][3], ad ^ 64u);
            }
            #pragma unroll
            for (int pr = 0; pr < 2; ++pr) {
                uint32_t bh[4], bl[4];
                const uint32_t bd = Bb + b_off[pr][s];
                LDM_X4(bh[0], bh[1], bh[2], bh[3], bd);
                LDM_X4(bl[0], bl[1], bl[2], bl[3], bd ^ 64u);
                #pragma unroll
                for (int mi = 0; mi < 4; ++mi) {
                    MMA_BF16(acc[mi][2 * pr + 0], ah[mi], bh[0], bh[1]);
                    MMA_BF16(acc[mi][2 * pr + 1], ah[mi], bh[2], bh[3]);
                    MMA_BF16(acc[mi][2 * pr + 0], al[mi], bh[0], bh[1]);
                    MMA_BF16(acc[mi][2 * pr + 1], al[mi], bh[2], bh[3]);
                    MMA_BF16(acc[mi][2 * pr + 0], ah[mi], bl[0], bl[1]);
                    MMA_BF16(acc[mi][2 * pr + 1], ah[mi], bl[2], bl[3]);
                }
            }
        }
        __syncthreads();
    }

    // ---- epilogue: bias + store ----
    #pragma unroll
    for (int nj = 0; nj < 4; ++nj) {
        const int n = n0 + wn + nj * 8 + (lid & 3) * 2;
        const float bx = bias[n], by = bias[n + 1];
        #pragma unroll
        for (int mi = 0; mi < 4; ++mi) {
            #pragma unroll
            for (int half = 0; half < 2; ++half) {
                const int m = m0 + wm + mi * 16 + (lid >> 2) + half * 8;
                float2 r;
                r.x = acc[mi][nj][2 * half + 0] + bx;
                r.y = acc[mi][nj][2 * half + 1] + by;
                size_t idx;
                if (SPLIT) {
                    const int b = m >> 11, t = m & (TT - 1);
                    const int h = n >> 6, d = n & 63;
                    idx = (((size_t)b * HH + h) * TT + t) * DD + d;
                } else {
                    idx = (size_t)m * CC + n;
                }
                *(float2*)(out + idx) = r;
            }
        }
    }
}

// ---------------------------------------------------------------------------
// Flash attention, fp32 SIMT (unchanged)
// ---------------------------------------------------------------------------
__global__ void __launch_bounds__(256) attn_kernel(const float* __restrict__ q,
                                                   const float* __restrict__ k,
                                                   const float* __restrict__ v,
                                                   float* __restrict__ y)
{
    extern __shared__ float smemf[];
    float* Qs = smemf;
    float* KP = smemf + 64 * 64;
    float* Vs = KP + 64 * 65;

    const int tid = threadIdx.x;
    const int tx  = tid & 15;
    const int ty  = tid >> 4;
    const int bh  = blockIdx.y;
    const int qt0 = blockIdx.x * 64;

    const size_t base = (size_t)bh * TT * DD;
    const float* qb = q + base + (size_t)qt0 * DD;
    const float* kb = k + base;
    const float* vb = v + base;

    const int lr = tid >> 2;
    const int lc = (tid & 3) * 16;

    #pragma unroll
    for (int u = 0; u < 16; u += 4) {
        float4 t4 = *(const float4*)(qb + (size_t)lr * DD + lc + u);
        Qs[lr * 64 + lc + u + 0] = t4.x * 0.125f;
        Qs[lr * 64 + lc + u + 1] = t4.y * 0.125f;
        Qs[lr * 64 + lc + u + 2] = t4.z * 0.125f;
        Qs[lr * 64 + lc + u + 3] = t4.w * 0.125f;
    }

    float o[4][4] = {};
    float mrow[4], lrow[4];
    #pragma unroll
    for (int i = 0; i < 4; ++i) { mrow[i] = -1e30f; lrow[i] = 0.f; }

    for (int kt0 = 0; kt0 <= qt0; kt0 += 64) {
        __syncthreads();
        #pragma unroll
        for (int u = 0; u < 16; u += 4) {
            float4 k4 = *(const float4*)(kb + (size_t)(kt0 + lr) * DD + lc + u);
            float4 v4 = *(const float4*)(vb + (size_t)(kt0 + lr) * DD + lc + u);
            KP[lr * 65 + lc + u + 0] = k4.x;
            KP[lr * 65 + lc + u + 1] = k4.y;
            KP[lr * 65 + lc + u + 2] = k4.z;
            KP[lr * 65 + lc + u + 3] = k4.w;
            Vs[lr * 64 + lc + u + 0] = v4.x;
            Vs[lr * 64 + lc + u + 1] = v4.y;
            Vs[lr * 64 + lc + u + 2] = v4.z;
            Vs[lr * 64 + lc + u + 3] = v4.w;
        }
        __syncthreads();

        float s[4][4] = {};
        #pragma unroll 16
        for (int d = 0; d < 64; ++d) {
            float qv[4], kv[4];
            #pragma unroll
            for (int i = 0; i < 4; ++i) qv[i] = Qs[(ty * 4 + i) * 64 + d];
            #pragma unroll
            for (int j = 0; j < 4; ++j) kv[j] = KP[(tx * 4 + j) * 65 + d];
            #pragma unroll
            for (int i = 0; i < 4; ++i)
                #pragma unroll
                for (int j = 0; j < 4; ++j)
                    s[i][j] += qv[i] * kv[j];
        }

        if (kt0 == qt0) {
            #pragma unroll
            for (int i = 0; i < 4; ++i)
                #pragma unroll
                for (int j = 0; j < 4; ++j)
                    if (tx * 4 + j > ty * 4 + i) s[i][j] = -1e30f;
        }

        float alpha[4];
        #pragma unroll
        for (int i = 0; i < 4; ++i) {
            float mx = fmaxf(fmaxf(s[i][0], s[i][1]), fmaxf(s[i][2], s[i][3]));
            #pragma unroll
            for (int off = 8; off > 0; off >>= 1)
                mx = fmaxf(mx, __shfl_xor_sync(0xffffffffu, mx, off));
            float mnew = fmaxf(mrow[i], mx);
            alpha[i] = __expf(mrow[i] - mnew);
            mrow[i] = mnew;
        }

        float p[4][4];
        #pragma unroll
        for (int i = 0; i < 4; ++i) {
            float sum = 0.f;
            #pragma unroll
            for (int j = 0; j < 4; ++j) {
                p[i][j] = __expf(s[i][j] - mrow[i]);
                sum += p[i][j];
            }
            #pragma unroll
            for (int off = 8; off > 0; off >>= 1)
                sum += __shfl_xor_sync(0xffffffffu, sum, off);
            lrow[i] = lrow[i] * alpha[i] + sum;
            #pragma unroll
            for (int j = 0; j < 4; ++j) o[i][j] *= alpha[i];
        }

        __syncthreads();
        #pragma unroll
        for (int i = 0; i < 4; ++i)
            #pragma unroll
            for (int j = 0; j < 4; ++j)
                KP[(ty * 4 + i) * 65 + tx * 4 + j] = p[i][j];
        __syncthreads();

        #pragma unroll 16
        for (int ss = 0; ss < 64; ++ss) {
            float pv[4], vv[4];
            #pragma unroll
            for (int i = 0; i < 4; ++i) pv[i] = KP[(ty * 4 + i) * 65 + ss];
            #pragma unroll
            for (int j = 0; j < 4; ++j) vv[j] = Vs[ss * 64 + tx * 4 + j];
            #pragma unroll
            for (int i = 0; i < 4; ++i)
                #pragma unroll
                for (int j = 0; j < 4; ++j)
                    o[i][j] += pv[i] * vv[j];
        }
    }

    const int b = bh / HH, h = bh % HH;
    #pragma unroll
    for (int i = 0; i < 4; ++i) {
        const int t = qt0 + ty * 4 + i;
        const float inv = 1.f / lrow[i];
        float4 r;
        r.x = o[i][0] * inv;
        r.y = o[i][1] * inv;
        r.z = o[i][2] * inv;
        r.w = o[i][3] * inv;
        size_t idx = ((size_t)b * TT + t) * CC + h * DD + tx * 4;
        *(float4*)(y + idx) = r;
    }
}

// ---------------------------------------------------------------------------
// Launch
// ---------------------------------------------------------------------------
extern "C" void kernel_launch(void* const* d_in, const int* in_sizes, int n_in,
                              void* d_out, int out_size)
{
    (void)in_sizes; (void)n_in; (void)out_size;
    const float* x  = (const float*)d_in[0];
    const float* Wk = (const float*)d_in[1];
    const float* bk = (const float*)d_in[2];
    const float* Wq = (const float*)d_in[3];
    const float* bq = (const float*)d_in[4];
    const float* Wv = (const float*)d_in[5];
    const float* bv = (const float*)d_in[6];
    const float* Wp = (const float*)d_in[7];
    const float* bp = (const float*)d_in[8];
    float* out = (float*)d_out;

    float *pq, *pk, *pv, *py;
    cudaGetSymbolAddress((void**)&pq, g_q);
    cudaGetSymbolAddress((void**)&pk, g_k);
    cudaGetSymbolAddress((void**)&pv, g_v);
    cudaGetSymbolAddress((void**)&py, g_y);
    __nv_bfloat16 *xhi, *xlo, *yhi, *ylo;
    __nv_bfloat16 *wqh, *wql, *wkh, *wkl, *wvh, *wvl, *wph, *wpl;
    cudaGetSymbolAddress((void**)&xhi, g_xhi);
    cudaGetSymbolAddress((void**)&xlo, g_xlo);
    cudaGetSymbolAddress((void**)&yhi, g_yhi);
    cudaGetSymbolAddress((void**)&ylo, g_ylo);
    cudaGetSymbolAddress((void**)&wqh, g_wq_hi);
    cudaGetSymbolAddress((void**)&wql, g_wq_lo);
    cudaGetSymbolAddress((void**)&wkh, g_wk_hi);
    cudaGetSymbolAddress((void**)&wkl, g_wk_lo);
    cudaGetSymbolAddress((void**)&wvh, g_wv_hi);
    cudaGetSymbolAddress((void**)&wvl, g_wv_lo);
    cudaGetSymbolAddress((void**)&wph, g_wp_hi);
    cudaGetSymbolAddress((void**)&wpl, g_wp_lo);

    const int xN4 = MM * CC / 4;
    const int wN4 = CC * CC / 4;
    cvt_hilo<<<(xN4 + 255) / 256, 256>>>(x, xhi, xlo, xN4);
    cvt_hilo<<<(wN4 + 255) / 256, 256>>>(Wq, wqh, wql, wN4);
    cvt_hilo<<<(wN4 + 255) / 256, 256>>>(Wk, wkh, wkl, wN4);
    cvt_hilo<<<(wN4 + 255) / 256, 256>>>(Wv, wvh, wvl, wN4);
    cvt_hilo<<<(wN4 + 255) / 256, 256>>>(Wp, wph, wpl, wN4);

    cudaFuncSetAttribute(mma_gemm<true>,  cudaFuncAttributeMaxDynamicSharedMemorySize, GEMM_SMEM);
    cudaFuncSetAttribute(mma_gemm<false>, cudaFuncAttributeMaxDynamicSharedMemorySize, GEMM_SMEM);

    dim3 gg(CC / 128, MM / 128);   // (8, 64)
    mma_gemm<true><<<gg, 256, GEMM_SMEM>>>(xhi, xlo, wqh, wql, bq, pq);
    mma_gemm<true><<<gg, 256, GEMM_SMEM>>>(xhi, xlo, wkh, wkl, bk, pk);
    mma_gemm<true><<<gg, 256, GEMM_SMEM>>>(xhi, xlo, wvh, wvl, bv, pv);

    const int attn_smem = (64 * 64 + 64 * 65 + 64 * 64) * (int)sizeof(float);
    cudaFuncSetAttribute(attn_kernel, cudaFuncAttributeMaxDynamicSharedMemorySize, attn_smem);
    attn_kernel<<<dim3(TT / 64, BB * HH), 256, attn_smem>>>(pq, pk, pv, py);

    cvt_hilo<<<(xN4 + 255) / 256, 256>>>(py, yhi, ylo, xN4);
    mma_gemm<false><<<gg, 256, GEMM_SMEM>>>(yhi, ylo, wph, wpl, bp, out);
}

// round 6
// speedup vs baseline: 3.3815x; 2.8531x over previous
#include <cuda_runtime.h>
#include <cuda_bf16.h>
#include <math.h>
#include <stdint.h>

// Problem constants
#define BB 4
#define TT 2048
#define CC 1024
#define HH 16
#define DD 64
#define MM (BB*TT)   // 8192 rows

// ---------------------------------------------------------------------------
// Scratch (__device__ globals; no allocation allowed)
// ---------------------------------------------------------------------------
__device__ __nv_bfloat16 g_xhi[(size_t)MM * CC];
__device__ __nv_bfloat16 g_xlo[(size_t)MM * CC];
__device__ __nv_bfloat16 g_qh[(size_t)MM * CC];   // (b,h,t,d)
__device__ __nv_bfloat16 g_ql[(size_t)MM * CC];
__device__ __nv_bfloat16 g_kh[(size_t)MM * CC];
__device__ __nv_bfloat16 g_kl[(size_t)MM * CC];
__device__ __nv_bfloat16 g_vh[(size_t)MM * CC];
__device__ __nv_bfloat16 g_vl[(size_t)MM * CC];
__device__ __nv_bfloat16 g_yh[(size_t)MM * CC];   // (b,t,c)
__device__ __nv_bfloat16 g_yl[(size_t)MM * CC];
__device__ __nv_bfloat16 g_wq_hi[(size_t)CC * CC];
__device__ __nv_bfloat16 g_wq_lo[(size_t)CC * CC];
__device__ __nv_bfloat16 g_wk_hi[(size_t)CC * CC];
__device__ __nv_bfloat16 g_wk_lo[(size_t)CC * CC];
__device__ __nv_bfloat16 g_wv_hi[(size_t)CC * CC];
__device__ __nv_bfloat16 g_wv_lo[(size_t)CC * CC];
__device__ __nv_bfloat16 g_wp_hi[(size_t)CC * CC];
__device__ __nv_bfloat16 g_wp_lo[(size_t)CC * CC];

// ---------------------------------------------------------------------------
// Helpers: cp.async, ldmatrix, mma.sync (baseline PTX only)
// ---------------------------------------------------------------------------
__device__ __forceinline__ uint32_t smem_u32(const void* p) {
    uint32_t a;
    asm("{ .reg .u64 t; cvta.to.shared.u64 t, %1; cvt.u32.u64 %0, t; }" : "=r"(a) : "l"(p));
    return a;
}
#define CP_ASYNC16(dst, src) \
    asm volatile("cp.async.cg.shared.global [%0], [%1], 16;" :: "r"(dst), "l"(src) : "memory")
#define CP_COMMIT() asm volatile("cp.async.commit_group;" ::: "memory")
#define CP_WAIT0()  asm volatile("cp.async.wait_group 0;" ::: "memory")
#define CP_WAIT1()  asm volatile("cp.async.wait_group 1;" ::: "memory")
#define CP_WAIT2()  asm volatile("cp.async.wait_group 2;" ::: "memory")

#define LDM_X4(r0, r1, r2, r3, a) \
    asm volatile("ldmatrix.sync.aligned.m8n8.x4.shared.b16 {%0,%1,%2,%3}, [%4];" \
        : "=r"(r0), "=r"(r1), "=r"(r2), "=r"(r3) : "r"(a))
#define LDM_X4T(r0, r1, r2, r3, a) \
    asm volatile("ldmatrix.sync.aligned.m8n8.x4.trans.shared.b16 {%0,%1,%2,%3}, [%4];" \
        : "=r"(r0), "=r"(r1), "=r"(r2), "=r"(r3) : "r"(a))

#define MMA_BF16(acc, a, b0, b1) \
    asm volatile("mma.sync.aligned.m16n8k16.row.col.f32.bf16.bf16.f32 " \
        "{%0,%1,%2,%3},{%4,%5,%6,%7},{%8,%9},{%0,%1,%2,%3};" \
        : "+f"((acc)[0]), "+f"((acc)[1]), "+f"((acc)[2]), "+f"((acc)[3]) \
        : "r"((a)[0]), "r"((a)[1]), "r"((a)[2]), "r"((a)[3]), "r"(b0), "r"(b1))

#define SWZ(x) ((x) ^ (((x) >> 3) & 0x70))

__device__ __forceinline__ uint32_t pack_bf16(float x, float y) {
    __nv_bfloat162 h = __float22bfloat162_rn(make_float2(x, y));
    return *(uint32_t*)&h;
}
__device__ __forceinline__ float2 unpack_bf16(uint32_t u) {
    __nv_bfloat162 h = *(__nv_bfloat162*)&u;
    return __bfloat1622float2(h);
}

// ---------------------------------------------------------------------------
// fp32 -> (bf16 hi, bf16 lo) split conversion
// ---------------------------------------------------------------------------
__global__ void __launch_bounds__(256) cvt_hilo(const float* __restrict__ src,
                                                __nv_bfloat16* __restrict__ hi,
                                                __nv_bfloat16* __restrict__ lo,
                                                int n4)
{
    int i = blockIdx.x * blockDim.x + threadIdx.x;
    if (i >= n4) return;
    float4 v = ((const float4*)src)[i];
    __nv_bfloat16 h0 = __float2bfloat16(v.x);
    __nv_bfloat16 h1 = __float2bfloat16(v.y);
    __nv_bfloat16 h2 = __float2bfloat16(v.z);
    __nv_bfloat16 h3 = __float2bfloat16(v.w);
    __nv_bfloat16 l0 = __float2bfloat16(v.x - __bfloat162float(h0));
    __nv_bfloat16 l1 = __float2bfloat16(v.y - __bfloat162float(h1));
    __nv_bfloat16 l2 = __float2bfloat16(v.z - __bfloat162float(h2));
    __nv_bfloat16 l3 = __float2bfloat16(v.w - __bfloat162float(h3));
    ((__nv_bfloat162*)hi)[2 * i + 0] = __nv_bfloat162(h0, h1);
    ((__nv_bfloat162*)hi)[2 * i + 1] = __nv_bfloat162(h2, h3);
    ((__nv_bfloat162*)lo)[2 * i + 0] = __nv_bfloat162(l0, l1);
    ((__nv_bfloat162*)lo)[2 * i + 1] = __nv_bfloat162(l2, l3);
}

// ---------------------------------------------------------------------------
// mma.sync GEMM: out(M,N) = (A(M,K) @ B(N,K)^T + bias) * scale, hi/lo bf16.
// MODE 0: fp32 row-major output. MODE 1: bf16 hi/lo head-split output.
// CTA 128x128, 8 warps (2m x 4n) of 64x32, K-chunk 32, 3-stage cp.async.
// ---------------------------------------------------------------------------
#define KC 32
#define NCH (CC / KC)
#define STG_A 16384
#define STG_BYTES 32768
#define GEMM_SMEM (3 * STG_BYTES)

template<int MODE>
__global__ void __launch_bounds__(256) mma_gemm(
    const __nv_bfloat16* __restrict__ Ahi, const __nv_bfloat16* __restrict__ Alo,
    const __nv_bfloat16* __restrict__ Bhi, const __nv_bfloat16* __restrict__ Blo,
    const float* __restrict__ bias, float* __restrict__ outF,
    __nv_bfloat16* __restrict__ outH, __nv_bfloat16* __restrict__ outL,
    float scale)
{
    extern __shared__ char smem[];
    const uint32_t sbase = smem_u32(smem);
    const int tid = threadIdx.x;
    const int wid = tid >> 5;
    const int lid = tid & 31;
    const int m0 = blockIdx.y * 128;
    const int n0 = blockIdx.x * 128;
    const int wm = (wid & 1) * 64;
    const int wn = (wid >> 1) * 32;

    uint32_t l_dst[8];
    const __nv_bfloat16* l_src[8];
    #pragma unroll
    for (int it = 0; it < 8; ++it) {
        const int u = it * 256 + tid;
        const bool isA = u < 1024;
        const int v = isA ? u : u - 1024;
        const int r = v >> 3, sub = v & 7;
        const int cbyte = (sub & 3) * 16 + (sub >> 2) * 64;
        l_dst[it] = sbase + (isA ? 0 : STG_A) + SWZ(r * 128 + cbyte);
        const __nv_bfloat16* basep = isA ? ((sub < 4) ? Ahi : Alo)
                                         : ((sub < 4) ? Bhi : Blo);
        const int row = isA ? (m0 + r) : (n0 + r);
        l_src[it] = basep + (size_t)row * CC + (sub & 3) * 8;
    }

    uint32_t a_off[4][2], b_off[2][2];
    #pragma unroll
    for (int mi = 0; mi < 4; ++mi)
        #pragma unroll
        for (int s = 0; s < 2; ++s) {
            const int r = wm + mi * 16 + (lid & 15);
            const int cb = s * 32 + ((lid >> 4) << 4);
            a_off[mi][s] = SWZ(r * 128 + cb);
        }
    #pragma unroll
    for (int pr = 0; pr < 2; ++pr)
        #pragma unroll
        for (int s = 0; s < 2; ++s) {
            const int r = wn + pr * 16 + (lid & 7) + ((lid >> 4) << 3);
            const int cb = s * 32 + (((lid >> 3) & 1) << 4);
            b_off[pr][s] = SWZ(r * 128 + cb);
        }

    float acc[4][4][4];
    #pragma unroll
    for (int i = 0; i < 4; ++i)
        #pragma unroll
        for (int j = 0; j < 4; ++j)
            #pragma unroll
            for (int e = 0; e < 4; ++e) acc[i][j][e] = 0.f;

    #pragma unroll
    for (int c = 0; c < 2; ++c) {
        const uint32_t so = c * STG_BYTES;
        #pragma unroll
        for (int it = 0; it < 8; ++it)
            CP_ASYNC16(l_dst[it] + so, l_src[it] + c * KC);
        CP_COMMIT();
    }

    for (int ch = 0; ch < NCH; ++ch) {
        const int nxt = ch + 2;
        if (nxt < NCH) {
            const uint32_t so = (nxt % 3) * STG_BYTES;
            #pragma unroll
            for (int it = 0; it < 8; ++it)
                CP_ASYNC16(l_dst[it] + so, l_src[it] + nxt * KC);
        }
        CP_COMMIT();
        CP_WAIT2();
        __syncthreads();

        const uint32_t Ab = sbase + (ch % 3) * STG_BYTES;
        const uint32_t Bb = Ab + STG_A;

        #pragma unroll
        for (int s = 0; s < 2; ++s) {
            uint32_t ah[4][4], al[4][4];
            #pragma unroll
            for (int mi = 0; mi < 4; ++mi) {
                const uint32_t ad = Ab + a_off[mi][s];
                LDM_X4(ah[mi][0], ah[mi][1], ah[mi][2], ah[mi][3], ad);
                LDM_X4(al[mi][0], al[mi][1], al[mi][2], al[mi][3], ad ^ 64u);
            }
            #pragma unroll
            for (int pr = 0; pr < 2; ++pr) {
                uint32_t bh[4], bl[4];
                const uint32_t bd = Bb + b_off[pr][s];
                LDM_X4(bh[0], bh[1], bh[2], bh[3], bd);
                LDM_X4(bl[0], bl[1], bl[2], bl[3], bd ^ 64u);
                #pragma unroll
                for (int mi = 0; mi < 4; ++mi) {
                    MMA_BF16(acc[mi][2 * pr + 0], ah[mi], bh[0], bh[1]);
                    MMA_BF16(acc[mi][2 * pr + 1], ah[mi], bh[2], bh[3]);
                    MMA_BF16(acc[mi][2 * pr + 0], al[mi], bh[0], bh[1]);
                    MMA_BF16(acc[mi][2 * pr + 1], al[mi], bh[2], bh[3]);
                    MMA_BF16(acc[mi][2 * pr + 0], ah[mi], bl[0], bl[1]);
                    MMA_BF16(acc[mi][2 * pr + 1], ah[mi], bl[2], bl[3]);
                }
            }
        }
        __syncthreads();
    }

    // epilogue
    #pragma unroll
    for (int nj = 0; nj < 4; ++nj) {
        const int n = n0 + wn + nj * 8 + (lid & 3) * 2;
        const float bx = bias[n], by = bias[n + 1];
        #pragma unroll
        for (int mi = 0; mi < 4; ++mi) {
            #pragma unroll
            for (int half = 0; half < 2; ++half) {
                const int m = m0 + wm + mi * 16 + (lid >> 2) + half * 8;
                const float rx = (acc[mi][nj][2 * half + 0] + bx) * scale;
                const float ry = (acc[mi][nj][2 * half + 1] + by) * scale;
                if (MODE == 0) {
                    float2 r; r.x = rx; r.y = ry;
                    *(float2*)(outF + (size_t)m * CC + n) = r;
                } else {
                    const int b = m >> 11, t = m & (TT - 1);
                    const int h = n >> 6, d = n & 63;
                    const size_t idx = (((size_t)b * HH + h) * TT + t) * DD + d;
                    const uint32_t hp = pack_bf16(rx, ry);
                    const float2 hv = unpack_bf16(hp);
                    const uint32_t lp = pack_bf16(rx - hv.x, ry - hv.y);
                    *(uint32_t*)(outH + idx) = hp;
                    *(uint32_t*)(outL + idx) = lp;
                }
            }
        }
    }
}

// ---------------------------------------------------------------------------
// Flash attention with mma.sync (bf16 hi/lo, fp32 softmax).
// CTA: 128 q-rows of one (b,h); 8 warps x 16 rows; kv tiles of 64.
// SMEM: Qhi 16K | Qlo 16K | stage{0,1}: Khi 8K, Klo 8K, Vhi 8K, Vlo 8K.
// ---------------------------------------------------------------------------
#define ATT_STG 32768
#define ATT_SMEM (32768 + 2 * ATT_STG)

__global__ void __launch_bounds__(256) attn_mma(
    const __nv_bfloat16* __restrict__ qh, const __nv_bfloat16* __restrict__ ql,
    const __nv_bfloat16* __restrict__ kh, const __nv_bfloat16* __restrict__ kl,
    const __nv_bfloat16* __restrict__ vh, const __nv_bfloat16* __restrict__ vl,
    __nv_bfloat16* __restrict__ yhi, __nv_bfloat16* __restrict__ ylo)
{
    extern __shared__ char smem[];
    const uint32_t sb = smem_u32(smem);
    const int tid = threadIdx.x;
    const int wid = tid >> 5;
    const int lid = tid & 31;
    const int qt0 = blockIdx.x * 128;
    const int bh = blockIdx.y;
    const int wm = wid * 16;
    const size_t hb = (size_t)bh * TT * DD;

    const __nv_bfloat16* khp = kh + hb;
    const __nv_bfloat16* klp = kl + hb;
    const __nv_bfloat16* vhp = vh + hb;
    const __nv_bfloat16* vlp = vl + hb;

    // --- Q tile load (once) ---
    #pragma unroll
    for (int it = 0; it < 8; ++it) {
        const int arr = it >> 2;                 // 0=hi, 1=lo
        const int v = ((it & 3) << 8) + tid;     // 0..1023
        const int r = v >> 3, c = v & 7;
        const __nv_bfloat16* p = (arr ? ql : qh) + hb + (size_t)(qt0 + r) * DD + c * 8;
        CP_ASYNC16(sb + arr * 16384 + SWZ(r * 128 + c * 16), p);
    }
    CP_COMMIT();

    const int ntiles = 2 * blockIdx.x + 2;

    // --- kv issue helper (stage: 0/1) ---
    auto issue_kv = [&](int t, int stage) {
        const int kt0 = t * 64;
        #pragma unroll
        for (int it = 0; it < 8; ++it) {
            const int arr = it >> 1;             // 0=kh,1=kl,2=vh,3=vl
            const int v = ((it & 1) << 8) + tid; // 0..511
            const int r = v >> 3, c = v & 7;
            const __nv_bfloat16* p = (arr == 0) ? khp : (arr == 1) ? klp
                                    : (arr == 2) ? vhp : vlp;
            CP_ASYNC16(sb + 32768 + stage * ATT_STG + arr * 8192 + SWZ(r * 128 + c * 16),
                       p + (size_t)(kt0 + r) * DD + c * 8);
        }
        CP_COMMIT();
    };

    issue_kv(0, 0);
    CP_WAIT1();          // Q done
    __syncthreads();

    // --- Q fragments (held in registers for whole kernel) ---
    uint32_t aqh[4][4], aql[4][4];
    {
        const int ar = wm + (lid & 15);
        const int ac = (lid >> 4) << 4;
        #pragma unroll
        for (int s = 0; s < 4; ++s) {
            const uint32_t off = SWZ(ar * 128 + s * 32 + ac);
            LDM_X4(aqh[s][0], aqh[s][1], aqh[s][2], aqh[s][3], sb + off);
            LDM_X4(aql[s][0], aql[s][1], aql[s][2], aql[s][3], sb + 16384 + off);
        }
    }

    const int brow = (lid & 7) + ((lid >> 4) << 3);
    const int bcol = ((lid >> 3) & 1) << 4;
    const int vrow = (lid & 7) + (((lid >> 3) & 1) << 3);
    const int vcol = (lid >> 4) << 4;

    float oacc[8][4];
    #pragma unroll
    for (int j = 0; j < 8; ++j)
        #pragma unroll
        for (int e = 0; e < 4; ++e) oacc[j][e] = 0.f;
    float m0 = -1e30f, m1 = -1e30f, l0 = 0.f, l1 = 0.f;

    const int row0 = qt0 + wm + (lid >> 2);
    const int row1 = row0 + 8;
    const int colb = 2 * (lid & 3);

    for (int t = 0; t < ntiles; ++t) {
        if (t + 1 < ntiles) { issue_kv(t + 1, (t + 1) & 1); CP_WAIT1(); }
        else CP_WAIT0();
        __syncthreads();

        const int kt0 = t * 64;
        if (kt0 <= qt0 + wm + 15) {
            const uint32_t stg = sb + 32768 + (t & 1) * ATT_STG;
            const uint32_t kH = stg, kL = stg + 8192;
            const uint32_t vH = stg + 16384, vL = stg + 24576;

            // ---- S = Q K^T ----
            float sacc[8][4];
            #pragma unroll
            for (int j = 0; j < 8; ++j)
                #pragma unroll
                for (int e = 0; e < 4; ++e) sacc[j][e] = 0.f;

            #pragma unroll
            for (int s = 0; s < 4; ++s) {
                #pragma unroll
                for (int pr = 0; pr < 4; ++pr) {
                    const uint32_t boff = SWZ((pr * 16 + brow) * 128 + s * 32 + bcol);
                    uint32_t bh0, bh1, bh2, bh3, bl0, bl1, bl2, bl3;
                    LDM_X4(bh0, bh1, bh2, bh3, kH + boff);
                    LDM_X4(bl0, bl1, bl2, bl3, kL + boff);
                    MMA_BF16(sacc[2 * pr + 0], aqh[s], bh0, bh1);
                    MMA_BF16(sacc[2 * pr + 0], aql[s], bh0, bh1);
                    MMA_BF16(sacc[2 * pr + 0], aqh[s], bl0, bl1);
                    MMA_BF16(sacc[2 * pr + 1], aqh[s], bh2, bh3);
                    MMA_BF16(sacc[2 * pr + 1], aql[s], bh2, bh3);
                    MMA_BF16(sacc[2 * pr + 1], aqh[s], bl2, bl3);
                }
            }

            // ---- causal mask (diagonal region only) ----
            if (kt0 + 64 > qt0 + wm) {
                #pragma unroll
                for (int j = 0; j < 8; ++j) {
                    const int c0 = kt0 + j * 8 + colb;
                    if (c0 > row0)     sacc[j][0] = -1e30f;
                    if (c0 + 1 > row0) sacc[j][1] = -1e30f;
                    if (c0 > row1)     sacc[j][2] = -1e30f;
                    if (c0 + 1 > row1) sacc[j][3] = -1e30f;
                }
            }

            // ---- online softmax ----
            float mx0 = -1e30f, mx1 = -1e30f;
            #pragma unroll
            for (int j = 0; j < 8; ++j) {
                mx0 = fmaxf(mx0, fmaxf(sacc[j][0], sacc[j][1]));
                mx1 = fmaxf(mx1, fmaxf(sacc[j][2], sacc[j][3]));
            }
            mx0 = fmaxf(mx0, __shfl_xor_sync(0xffffffffu, mx0, 1));
            mx0 = fmaxf(mx0, __shfl_xor_sync(0xffffffffu, mx0, 2));
            mx1 = fmaxf(mx1, __shfl_xor_sync(0xffffffffu, mx1, 1));
            mx1 = fmaxf(mx1, __shfl_xor_sync(0xffffffffu, mx1, 2));
            const float mn0 = fmaxf(m0, mx0), mn1 = fmaxf(m1, mx1);
            const float al0 = __expf(m0 - mn0), al1 = __expf(m1 - mn1);
            m0 = mn0; m1 = mn1;

            float rs0 = 0.f, rs1 = 0.f;
            #pragma unroll
            for (int j = 0; j < 8; ++j) {
                sacc[j][0] = __expf(sacc[j][0] - m0);
                sacc[j][1] = __expf(sacc[j][1] - m0);
                sacc[j][2] = __expf(sacc[j][2] - m1);
                sacc[j][3] = __expf(sacc[j][3] - m1);
                rs0 += sacc[j][0] + sacc[j][1];
                rs1 += sacc[j][2] + sacc[j][3];
            }
            rs0 += __shfl_xor_sync(0xffffffffu, rs0, 1);
            rs0 += __shfl_xor_sync(0xffffffffu, rs0, 2);
            rs1 += __shfl_xor_sync(0xffffffffu, rs1, 1);
            rs1 += __shfl_xor_sync(0xffffffffu, rs1, 2);
            l0 = l0 * al0 + rs0;
            l1 = l1 * al1 + rs1;
            #pragma unroll
            for (int j = 0; j < 8; ++j) {
                oacc[j][0] *= al0; oacc[j][1] *= al0;
                oacc[j][2] *= al1; oacc[j][3] *= al1;
            }

            // ---- O += P V ----
            #pragma unroll
            for (int kk = 0; kk < 4; ++kk) {
                const int j0 = 2 * kk, j1 = j0 + 1;
                uint32_t ph[4], pl[4];
                {
                    const uint32_t h0 = pack_bf16(sacc[j0][0], sacc[j0][1]);
                    const uint32_t h1 = pack_bf16(sacc[j0][2], sacc[j0][3]);
                    const uint32_t h2 = pack_bf16(sacc[j1][0], sacc[j1][1]);
                    const uint32_t h3 = pack_bf16(sacc[j1][2], sacc[j1][3]);
                    ph[0] = h0; ph[1] = h1; ph[2] = h2; ph[3] = h3;
                    const float2 f0 = unpack_bf16(h0), f1 = unpack_bf16(h1);
                    const float2 f2 = unpack_bf16(h2), f3 = unpack_bf16(h3);
                    pl[0] = pack_bf16(sacc[j0][0] - f0.x, sacc[j0][1] - f0.y);
                    pl[1] = pack_bf16(sacc[j0][2] - f1.x, sacc[j0][3] - f1.y);
                    pl[2] = pack_bf16(sacc[j1][0] - f2.x, sacc[j1][1] - f2.y);
                    pl[3] = pack_bf16(sacc[j1][2] - f3.x, sacc[j1][3] - f3.y);
                }
                #pragma unroll
                for (int dd = 0; dd < 4; ++dd) {
                    const uint32_t voff = SWZ((kk * 16 + vrow) * 128 + dd * 32 + vcol);
                    uint32_t vh0, vh1, vh2, vh3, vl0, vl1, vl2, vl3;
                    LDM_X4T(vh0, vh1, vh2, vh3, vH + voff);
                    LDM_X4T(vl0, vl1, vl2, vl3, vL + voff);
                    MMA_BF16(oacc[2 * dd + 0], ph, vh0, vh1);
                    MMA_BF16(oacc[2 * dd + 0], pl, vh0, vh1);
                    MMA_BF16(oacc[2 * dd + 0], ph, vl0, vl1);
                    MMA_BF16(oacc[2 * dd + 1], ph, vh2, vh3);
                    MMA_BF16(oacc[2 * dd + 1], pl, vh2, vh3);
                    MMA_BF16(oacc[2 * dd + 1], ph, vl2, vl3);
                }
            }
        }
        __syncthreads();
    }

    // ---- epilogue: normalize, split hi/lo, write (b,t,c) ----
    const int b = bh >> 4, h = bh & 15;
    const float inv0 = 1.f / l0, inv1 = 1.f / l1;
    const int t0r = row0, t1r = row1;   // global t indices
    #pragma unroll
    for (int j = 0; j < 8; ++j) {
        const int d = j * 8 + colb;
        const float o0 = oacc[j][0] * inv0, o1 = oacc[j][1] * inv0;
        const float o2 = oacc[j][2] * inv1, o3 = oacc[j][3] * inv1;
        const size_t i0 = ((size_t)b * TT + t0r) * CC + h * DD + d;
        const size_t i1 = ((size_t)b * TT + t1r) * CC + h * DD + d;
        const uint32_t h0 = pack_bf16(o0, o1);
        const float2 f0 = unpack_bf16(h0);
        const uint32_t lo0 = pack_bf16(o0 - f0.x, o1 - f0.y);
        const uint32_t h1 = pack_bf16(o2, o3);
        const float2 f1 = unpack_bf16(h1);
        const uint32_t lo1 = pack_bf16(o2 - f1.x, o3 - f1.y);
        *(uint32_t*)(yhi + i0) = h0;
        *(uint32_t*)(ylo + i0) = lo0;
        *(uint32_t*)(yhi + i1) = h1;
        *(uint32_t*)(ylo + i1) = lo1;
    }
}

// ---------------------------------------------------------------------------
// Launch
// ---------------------------------------------------------------------------
extern "C" void kernel_launch(void* const* d_in, const int* in_sizes, int n_in,
                              void* d_out, int out_size)
{
    (void)in_sizes; (void)n_in; (void)out_size;
    const float* x  = (const float*)d_in[0];
    const float* Wk = (const float*)d_in[1];
    const float* bk = (const float*)d_in[2];
    const float* Wq = (const float*)d_in[3];
    const float* bq = (const float*)d_in[4];
    const float* Wv = (const float*)d_in[5];
    const float* bv = (const float*)d_in[6];
    const float* Wp = (const float*)d_in[7];
    const float* bp = (const float*)d_in[8];
    float* out = (float*)d_out;

    __nv_bfloat16 *xhi, *xlo, *qh, *ql, *kh, *kl, *vh, *vl, *yh, *yl;
    __nv_bfloat16 *wqh, *wql, *wkh, *wkl, *wvh, *wvl, *wph, *wpl;
    cudaGetSymbolAddress((void**)&xhi, g_xhi);
    cudaGetSymbolAddress((void**)&xlo, g_xlo);
    cudaGetSymbolAddress((void**)&qh, g_qh);
    cudaGetSymbolAddress((void**)&ql, g_ql);
    cudaGetSymbolAddress((void**)&kh, g_kh);
    cudaGetSymbolAddress((void**)&kl, g_kl);
    cudaGetSymbolAddress((void**)&vh, g_vh);
    cudaGetSymbolAddress((void**)&vl, g_vl);
    cudaGetSymbolAddress((void**)&yh, g_yh);
    cudaGetSymbolAddress((void**)&yl, g_yl);
    cudaGetSymbolAddress((void**)&wqh, g_wq_hi);
    cudaGetSymbolAddress((void**)&wql, g_wq_lo);
    cudaGetSymbolAddress((void**)&wkh, g_wk_hi);
    cudaGetSymbolAddress((void**)&wkl, g_wk_lo);
    cudaGetSymbolAddress((void**)&wvh, g_wv_hi);
    cudaGetSymbolAddress((void**)&wvl, g_wv_lo);
    cudaGetSymbolAddress((void**)&wph, g_wp_hi);
    cudaGetSymbolAddress((void**)&wpl, g_wp_lo);

    const int xN4 = MM * CC / 4;
    const int wN4 = CC * CC / 4;
    cvt_hilo<<<(xN4 + 255) / 256, 256>>>(x, xhi, xlo, xN4);
    cvt_hilo<<<(wN4 + 255) / 256, 256>>>(Wq, wqh, wql, wN4);
    cvt_hilo<<<(wN4 + 255) / 256, 256>>>(Wk, wkh, wkl, wN4);
    cvt_hilo<<<(wN4 + 255) / 256, 256>>>(Wv, wvh, wvl, wN4);
    cvt_hilo<<<(wN4 + 255) / 256, 256>>>(Wp, wph, wpl, wN4);

    cudaFuncSetAttribute(mma_gemm<0>, cudaFuncAttributeMaxDynamicSharedMemorySize, GEMM_SMEM);
    cudaFuncSetAttribute(mma_gemm<1>, cudaFuncAttributeMaxDynamicSharedMemorySize, GEMM_SMEM);
    cudaFuncSetAttribute(attn_mma, cudaFuncAttributeMaxDynamicSharedMemorySize, ATT_SMEM);

    dim3 gg(CC / 128, MM / 128);   // (8, 64)
    mma_gemm<1><<<gg, 256, GEMM_SMEM>>>(xhi, xlo, wqh, wql, bq, nullptr, qh, ql, 0.125f);
    mma_gemm<1><<<gg, 256, GEMM_SMEM>>>(xhi, xlo, wkh, wkl, bk, nullptr, kh, kl, 1.0f);
    mma_gemm<1><<<gg, 256, GEMM_SMEM>>>(xhi, xlo, wvh, wvl, bv, nullptr, vh, vl, 1.0f);

    attn_mma<<<dim3(TT / 128, BB * HH), 256, ATT_SMEM>>>(qh, ql, kh, kl, vh, vl, yh, yl);

    mma_gemm<0><<<gg, 256, GEMM_SMEM>>>(yh, yl, wph, wpl, bp, out, nullptr, nullptr, 1.0f);
}